// round 3
// baseline (speedup 1.0000x reference)
#include <cuda_runtime.h>
#include <cstdint>

#define R  5
#define E  50000
#define NUx 20000
#define NIx 20000
#define NF 4
#define DN 16
#define DR 64
#define DO 64
// TAU = 0.5  ->  1/TAU = 2.0f

// ---------------- scratch (device globals; no allocation) ----------------
__device__ __align__(16) float g_blended[R * E];
__device__ float g_norm_user[NUx];
__device__ float g_norm_item[NIx];
__device__ __align__(16) float g_hu[R * NUx * DN];
__device__ __align__(16) float g_hi[R * NIx * DN];
__device__ __align__(16) float g_user_msg[NUx * DN];
__device__ __align__(16) float g_item_msg[NIx * DN];

// ---------------- kernel 1: zero accumulators ----------------
__global__ void zero_kernel() {
    int i = blockIdx.x * blockDim.x + threadIdx.x;   // covers NU*DN = 320000
    if (i < NUx) g_norm_user[i] = 0.f;
    if (i < NIx) g_norm_item[i] = 0.f;
    if (i < NUx * DN) g_user_msg[i] = 0.f;
    if (i < NIx * DN) g_item_msg[i] = 0.f;
}

// ---------------- kernel 2: hu = uh @ Wfwd^T, hi = ih @ Wrev^T ----------------
// thread per (r, n); blockIdx.y = side (0 user, 1 item)
__global__ void proj_kernel(const float* __restrict__ user_h,
                            const float* __restrict__ item_h,
                            const float* __restrict__ w_fwd,
                            const float* __restrict__ w_rev,
                            const int* __restrict__ kptr) {
    int idx = blockIdx.x * blockDim.x + threadIdx.x;
    if (idx >= R * NUx) return;
    int side = blockIdx.y;
    int r = idx / NUx, n = idx % NUx;
    int kk = *kptr;

    const float* h = (side ? item_h : user_h) + ((size_t)(kk * R + r) * NUx + n) * DN;
    const float* W = (side ? w_rev : w_fwd) + r * DN * DN;
    float* out = (side ? g_hi : g_hu) + ((size_t)r * NUx + n) * DN;

    float x[DN];
#pragma unroll
    for (int i = 0; i < 4; i++) {
        float4 t = reinterpret_cast<const float4*>(h)[i];
        x[4*i+0] = t.x; x[4*i+1] = t.y; x[4*i+2] = t.z; x[4*i+3] = t.w;
    }
#pragma unroll
    for (int o = 0; o < DN; o++) {
        float acc = 0.f;
#pragma unroll
        for (int d = 0; d < DN; d++) acc += x[d] * __ldg(&W[o * DN + d]);
        out[o] = acc;
    }
}

// ---------------- kernel 3: per-edge blended weight (warp per edge) ----------------
__global__ void edge_blend_kernel(const float* __restrict__ user_h,
                                  const float* __restrict__ item_h,
                                  const float* __restrict__ user_hsum,
                                  const float* __restrict__ item_hsum,
                                  const float* __restrict__ review_feat,
                                  const float* __restrict__ prototypes,
                                  const float* __restrict__ eta,
                                  const int* __restrict__ edge_src,
                                  const int* __restrict__ edge_dst,
                                  const int* __restrict__ kptr) {
    __shared__ float sproto[NF * DR];   // 256 floats
    int tid = threadIdx.x;
    if (tid < NF * DR) sproto[tid] = prototypes[tid];
    __syncthreads();

    int r = blockIdx.y;
    int e = blockIdx.x * (blockDim.x >> 5) + (tid >> 5);
    if (e >= E) return;
    int lane = tid & 31;
    int kk = *kptr;

    int src = edge_src[r * E + e];
    int dst = edge_dst[r * E + e];

    // --- cosine sim between l2-normalized user_h[k] / item_h[k] rows (DN=16) ---
    float u = 0.f, v = 0.f;
    if (lane < DN) {
        u = user_h[((size_t)(kk * R + r) * NUx + src) * DN + lane];
        v = item_h[((size_t)(kk * R + r) * NIx + dst) * DN + lane];
    }
    float uu = u * u, vv = v * v, uv = u * v;
#pragma unroll
    for (int off = 16; off >= 1; off >>= 1) {
        uu += __shfl_xor_sync(0xffffffffu, uu, off);
        vv += __shfl_xor_sync(0xffffffffu, vv, off);
        uv += __shfl_xor_sync(0xffffffffu, uv, off);
    }
    float nu_ = fmaxf(sqrtf(uu), 1e-12f);
    float nv_ = fmaxf(sqrtf(vv), 1e-12f);
    float sim_k = (uv / (nu_ * nv_)) * 2.0f;   // / TAU

    // --- sim_all over NF=4 factors (64 floats each side) ---
    const float* ra = user_hsum + (size_t)(r * NUx + src) * (NF * DN);
    const float* ca = item_hsum + (size_t)(r * NIx + dst) * (NF * DN);
    float p1 = ra[lane] * ca[lane];            // covers f0 (lanes 0-15), f1 (16-31)
    float p2 = ra[lane + 32] * ca[lane + 32];  // covers f2, f3
#pragma unroll
    for (int off = 8; off >= 1; off >>= 1) {
        p1 += __shfl_xor_sync(0xffffffffu, p1, off);
        p2 += __shfl_xor_sync(0xffffffffu, p2, off);
    }
    float dpart = __expf(2.f * p1) + __expf(2.f * p2);
    float denom_sim = dpart + __shfl_xor_sync(0xffffffffu, dpart, 16);
    float exp_sim = __expf(sim_k) / denom_sim;

    // --- anchors: review_feat[r,e,:,:] (256 contiguous floats) dot prototypes ---
    const float* rf = review_feat + ((size_t)r * E + e) * (NF * DR);
    float q[8];
#pragma unroll
    for (int j = 0; j < 8; j++) q[j] = rf[lane + 32 * j] * sproto[lane + 32 * j];
    float t0 = q[0] + q[1], t1 = q[2] + q[3], t2 = q[4] + q[5], t3 = q[6] + q[7];
#pragma unroll
    for (int off = 16; off >= 1; off >>= 1) {
        t0 += __shfl_xor_sync(0xffffffffu, t0, off);
        t1 += __shfl_xor_sync(0xffffffffu, t1, off);
        t2 += __shfl_xor_sync(0xffffffffu, t2, off);
        t3 += __shfl_xor_sync(0xffffffffu, t3, off);
    }
    float a0 = 2.f * t0, a1 = 2.f * t1, a2 = 2.f * t2, a3 = 2.f * t3;
    float denom_anchor = __expf(a0) + __expf(a1) + __expf(a2) + __expf(a3);
    float ak = (kk == 0) ? a0 : (kk == 1) ? a1 : (kk == 2) ? a2 : a3;
    float exp_anchor = __expf(ak) / denom_anchor;

    float gsig = 1.f / (1.f + __expf(-eta[r * E + e]));
    float blended = gsig * exp_anchor + (1.f - gsig) * exp_sim;

    if (lane == 0) {
        g_blended[r * E + e] = blended;
        atomicAdd(&g_norm_user[src], blended);
        atomicAdd(&g_norm_item[dst], blended);
    }
}

// vector global reduction (sm_90+): 4 floats in one RED
__device__ __forceinline__ void red_add_v4(float* p, float4 m) {
    asm volatile("red.global.add.v4.f32 [%0], {%1, %2, %3, %4};"
                 :: "l"(p), "f"(m.x), "f"(m.y), "f"(m.z), "f"(m.w)
                 : "memory");
}

// ---------------- kernel 4: normalize + messages (thread per edge) ----------------
__global__ void edge_msg_kernel(const float* __restrict__ review_feat,
                                const float* __restrict__ rw_fwd,
                                const float* __restrict__ rw_rev,
                                const int* __restrict__ edge_src,
                                const int* __restrict__ edge_dst,
                                const int* __restrict__ kptr,
                                float* __restrict__ out_int_dist) {
    __shared__ float4 sWf[DN * DR / 4];   // 16x64 fwd weights, one r
    __shared__ float4 sWr[DN * DR / 4];
    int r = blockIdx.y;
    int tid = threadIdx.x;

    const float4* wf4 = reinterpret_cast<const float4*>(rw_fwd + r * DN * DR);
    const float4* wr4 = reinterpret_cast<const float4*>(rw_rev + r * DN * DR);
    for (int i = tid; i < DN * DR / 4; i += blockDim.x) { sWf[i] = wf4[i]; sWr[i] = wr4[i]; }
    __syncthreads();

    int e = blockIdx.x * blockDim.x + tid;
    if (e >= E) return;

    int src = edge_src[r * E + e];
    int dst = edge_dst[r * E + e];
    float blended = g_blended[r * E + e];
    float w = blended * rsqrtf(g_norm_user[src] * g_norm_item[dst]);
    out_int_dist[r * E + e] = w;

    int kk = *kptr;
    const float4* rf4 = reinterpret_cast<const float4*>(
        review_feat + (((size_t)r * E + e) * NF + kk) * DR);

    float accF[DN], accR[DN];
#pragma unroll
    for (int o = 0; o < DN; o++) { accF[o] = 0.f; accR[o] = 0.f; }
#pragma unroll
    for (int d4 = 0; d4 < DR / 4; d4++) {
        float4 x = rf4[d4];
#pragma unroll
        for (int o = 0; o < DN; o++) {
            float4 wf = sWf[o * (DR / 4) + d4];
            accF[o] += x.x * wf.x + x.y * wf.y + x.z * wf.z + x.w * wf.w;
            float4 wr = sWr[o * (DR / 4) + d4];
            accR[o] += x.x * wr.x + x.y * wr.y + x.z * wr.z + x.w * wr.w;
        }
    }

    const float4* hu4 = reinterpret_cast<const float4*>(g_hu + ((size_t)r * NUx + src) * DN);
    const float4* hi4 = reinterpret_cast<const float4*>(g_hi + ((size_t)r * NIx + dst) * DN);
    float* im = g_item_msg + (size_t)dst * DN;
    float* um = g_user_msg + (size_t)src * DN;
#pragma unroll
    for (int i = 0; i < 4; i++) {
        float4 h = hu4[i];
        float4 mf = make_float4((h.x + accF[4*i+0]) * w, (h.y + accF[4*i+1]) * w,
                                (h.z + accF[4*i+2]) * w, (h.w + accF[4*i+3]) * w);
        red_add_v4(im + 4 * i, mf);
        float4 h2 = hi4[i];
        float4 mr = make_float4((h2.x + accR[4*i+0]) * w, (h2.y + accR[4*i+1]) * w,
                                (h2.z + accR[4*i+2]) * w, (h2.w + accR[4*i+3]) * w);
        red_add_v4(um + 4 * i, mr);
    }
}

// ---------------- kernel 5: leaky_relu + FC for users and items ----------------
__global__ void fc_kernel(const float* __restrict__ ufc_w, const float* __restrict__ ufc_b,
                          const float* __restrict__ ifc_w, const float* __restrict__ ifc_b,
                          float* __restrict__ out) {
    __shared__ float sW[2][DO * DN];
    __shared__ float sB[2][DO];
    int tid = threadIdx.x;   // 256
    for (int i = tid; i < DO * DN; i += 256) { sW[0][i] = ufc_w[i]; sW[1][i] = ifc_w[i]; }
    if (tid < DO) { sB[0][tid] = ufc_b[tid]; sB[1][tid] = ifc_b[tid]; }
    __syncthreads();

    int node = blockIdx.x * (256 / DO) + tid / DO;
    int o = tid % DO;
    if (node >= NUx + NIx) return;
    int side = node >= NUx;
    int n = side ? node - NUx : node;
    const float* msg = (side ? g_item_msg : g_user_msg) + (size_t)n * DN;

    float acc = sB[side][o];
#pragma unroll
    for (int d = 0; d < DN; d++) {
        float m = msg[d];
        m = (m >= 0.f) ? m : 0.1f * m;
        acc += m * sW[side][o * DN + d];
    }
    out[(size_t)node * DO + o] = acc;   // ufeat then ifeat, contiguous
}

// ---------------- launch ----------------
extern "C" void kernel_launch(void* const* d_in, const int* in_sizes, int n_in,
                              void* d_out, int out_size) {
    const float* user_h      = (const float*)d_in[0];
    const float* item_h      = (const float*)d_in[1];
    const float* user_hsum   = (const float*)d_in[2];
    const float* item_hsum   = (const float*)d_in[3];
    const float* review_feat = (const float*)d_in[4];
    const float* prototypes  = (const float*)d_in[5];
    const float* eta         = (const float*)d_in[6];
    const float* node_w_fwd  = (const float*)d_in[7];
    const float* review_w_fwd= (const float*)d_in[8];
    const float* node_w_rev  = (const float*)d_in[9];
    const float* review_w_rev= (const float*)d_in[10];
    const float* ufc_w       = (const float*)d_in[11];
    const float* ufc_b       = (const float*)d_in[12];
    const float* ifc_w       = (const float*)d_in[13];
    const float* ifc_b       = (const float*)d_in[14];
    const int*   edge_src    = (const int*)d_in[15];
    const int*   edge_dst    = (const int*)d_in[16];
    const int*   kptr        = (const int*)d_in[17];

    float* out = (float*)d_out;
    float* out_int = out + (size_t)(NUx + NIx) * DO;   // int_dist after ufeat+ifeat

    zero_kernel<<<(NUx * DN) / 256, 256>>>();

    dim3 gp((R * NUx + 255) / 256, 2);
    proj_kernel<<<gp, 256>>>(user_h, item_h, node_w_fwd, node_w_rev, kptr);

    dim3 ga(E / 8, R);  // 8 warps/block, warp per edge
    edge_blend_kernel<<<ga, 256>>>(user_h, item_h, user_hsum, item_hsum,
                                   review_feat, prototypes, eta,
                                   edge_src, edge_dst, kptr);

    dim3 gb((E + 255) / 256, R);
    edge_msg_kernel<<<gb, 256>>>(review_feat, review_w_fwd, review_w_rev,
                                 edge_src, edge_dst, kptr, out_int);

    fc_kernel<<<((NUx + NIx) * DO) / 256, 256>>>(ufc_w, ufc_b, ifc_w, ifc_b, out);
}